// round 1
// baseline (speedup 1.0000x reference)
#include <cuda_runtime.h>
#include <cuda_bf16.h>
#include <math.h>

// ---------------- problem constants ----------------
#define BB   4
#define NN   256
#define DD   384
#define LL   12
#define F1C  1536
#define F2C  384
#define MM   8
#define HH   4
#define TT   260          // 4 skill tokens + 256
#define DH   96           // D / H
#define ROWS (BB*TT)      // 1040

__device__ __forceinline__ int GCNT_f() { return LL*F1C*F2C; }
#define GCNT   (LL*F1C*F2C)          // 7,077,888
#define OUTROW (2LL*GCNT)            // 14,155,776 per batch row

// ---------------- device scratch (static, no allocation) ----------------
#define OFF_TOK  0
#define SZ_TOK   (ROWS*DD)                 // 399360
#define OFF_Y    (OFF_TOK + SZ_TOK)
#define SZ_Y     (ROWS*DD)
#define OFF_QKV  (OFF_Y + SZ_Y)
#define SZ_QKV   (ROWS*3*DD)               // 1198080
#define OFF_Q    (OFF_QKV + SZ_QKV)
#define SZ_Q     (BB*HH*TT*DH)             // 399360
#define OFF_KT   (OFF_Q + SZ_Q)
#define SZ_KT    (BB*HH*TT*DH)
#define OFF_V    (OFF_KT + SZ_KT)
#define SZ_V     (BB*HH*TT*DH)
#define OFF_SC   (OFF_V + SZ_V)
#define SZ_SC    (BB*HH*TT*TT)             // 1081600
#define OFF_O    (OFF_SC + SZ_SC)
#define SZ_O     (ROWS*DD)
#define OFF_FF   (OFF_O + SZ_O)
#define SZ_FF    (ROWS*2*DD)               // 798720
#define OFF_W    (OFF_FF + SZ_FF)
#define SZ_W     32
#define SCRATCH_TOTAL (OFF_W + SZ_W)

__device__ float g_scratch[SCRATCH_TOTAL];

// ---------------- generic batched GEMM: C = act(scale*(A@W) + bias [+R]) ----------------
// A: (Mr x K) row-major, lda=K.  W: (K x N) row-major.  C: ldc row stride.
// batch z: A += z*aBS, W += z*wBS, C += (z/cdiv)*cBS1 + (z%cdiv)*cBS2
// epi: 0=none, 1=gelu(tanh), 2=+R[col] broadcast, 3=+R[c_offset + row*ldc + col] residual
__global__ void __launch_bounds__(256) gemm_kernel(
    const float* __restrict__ A, const float* __restrict__ W,
    const float* __restrict__ bias, const float* __restrict__ R,
    float* __restrict__ C,
    int Mr, int N, int K,
    long long aBS, long long wBS, long long cBS1, long long cBS2, int cdiv,
    int ldc, float scale, int epi)
{
    int z = blockIdx.z;
    A += (size_t)z * aBS;
    W += (size_t)z * wBS;
    size_t coff = (size_t)(z / cdiv) * cBS1 + (size_t)(z % cdiv) * cBS2;
    C += coff;
    const float* Rm = (epi == 3) ? (R + coff) : R;

    __shared__ float As[16][64];
    __shared__ float Ws[16][64];

    int bm = blockIdx.y * 64, bn = blockIdx.x * 64;
    int tid = threadIdx.x;
    int tx = tid & 15, ty = tid >> 4;

    int la_m = tid >> 2;            // 0..63
    int la_k = (tid & 3) << 2;      // 0,4,8,12
    int lw_k = tid >> 4;            // 0..15
    int lw_n = (tid & 15) << 2;     // 0..60

    float acc[4][4];
#pragma unroll
    for (int i = 0; i < 4; i++)
#pragma unroll
        for (int j = 0; j < 4; j++) acc[i][j] = 0.f;

    for (int k0 = 0; k0 < K; k0 += 16) {
        float4 av = make_float4(0.f, 0.f, 0.f, 0.f);
        int arow = bm + la_m;
        if (arow < Mr && (k0 + la_k) < K)
            av = *(const float4*)(A + (size_t)arow * K + k0 + la_k);
        As[la_k + 0][la_m] = av.x;
        As[la_k + 1][la_m] = av.y;
        As[la_k + 2][la_m] = av.z;
        As[la_k + 3][la_m] = av.w;

        float4 wv = make_float4(0.f, 0.f, 0.f, 0.f);
        if ((k0 + lw_k) < K && (bn + lw_n) < N)
            wv = *(const float4*)(W + (size_t)(k0 + lw_k) * N + bn + lw_n);
        *(float4*)&Ws[lw_k][lw_n] = wv;

        __syncthreads();
#pragma unroll
        for (int kk = 0; kk < 16; kk++) {
            float4 a = *(const float4*)&As[kk][ty << 2];
            float4 w = *(const float4*)&Ws[kk][tx << 2];
            acc[0][0] = fmaf(a.x, w.x, acc[0][0]);
            acc[0][1] = fmaf(a.x, w.y, acc[0][1]);
            acc[0][2] = fmaf(a.x, w.z, acc[0][2]);
            acc[0][3] = fmaf(a.x, w.w, acc[0][3]);
            acc[1][0] = fmaf(a.y, w.x, acc[1][0]);
            acc[1][1] = fmaf(a.y, w.y, acc[1][1]);
            acc[1][2] = fmaf(a.y, w.z, acc[1][2]);
            acc[1][3] = fmaf(a.y, w.w, acc[1][3]);
            acc[2][0] = fmaf(a.z, w.x, acc[2][0]);
            acc[2][1] = fmaf(a.z, w.y, acc[2][1]);
            acc[2][2] = fmaf(a.z, w.z, acc[2][2]);
            acc[2][3] = fmaf(a.z, w.w, acc[2][3]);
            acc[3][0] = fmaf(a.w, w.x, acc[3][0]);
            acc[3][1] = fmaf(a.w, w.y, acc[3][1]);
            acc[3][2] = fmaf(a.w, w.z, acc[3][2]);
            acc[3][3] = fmaf(a.w, w.w, acc[3][3]);
        }
        __syncthreads();
    }

    int colb = bn + (tx << 2);
    if (colb >= N) return;
    float4 bv = make_float4(0.f, 0.f, 0.f, 0.f);
    if (bias) bv = *(const float4*)(bias + colb);
    float4 ev = make_float4(0.f, 0.f, 0.f, 0.f);
    if (epi == 2) ev = *(const float4*)(R + colb);

#pragma unroll
    for (int i = 0; i < 4; i++) {
        int row = bm + (ty << 2) + i;
        if (row >= Mr) continue;
        float4 r;
        r.x = acc[i][0] * scale + bv.x;
        r.y = acc[i][1] * scale + bv.y;
        r.z = acc[i][2] * scale + bv.z;
        r.w = acc[i][3] * scale + bv.w;
        if (epi == 1) {
            // tanh-gelu (jax default approximate=True)
            float v;
            v = r.x; r.x = 0.5f * v * (1.f + tanhf(0.7978845608028654f * (v + 0.044715f * v * v * v)));
            v = r.y; r.y = 0.5f * v * (1.f + tanhf(0.7978845608028654f * (v + 0.044715f * v * v * v)));
            v = r.z; r.z = 0.5f * v * (1.f + tanhf(0.7978845608028654f * (v + 0.044715f * v * v * v)));
            v = r.w; r.w = 0.5f * v * (1.f + tanhf(0.7978845608028654f * (v + 0.044715f * v * v * v)));
        } else if (epi == 2) {
            r.x += ev.x; r.y += ev.y; r.z += ev.z; r.w += ev.w;
        } else if (epi == 3) {
            float4 rv = *(const float4*)(Rm + (size_t)row * ldc + colb);
            r.x += rv.x; r.y += rv.y; r.z += rv.z; r.w += rv.w;
        }
        *(float4*)(C + (size_t)row * ldc + colb) = r;
    }
}

// ---------------- fill skill tokens ----------------
__global__ void fill_skills_kernel(const float* __restrict__ skills, float* __restrict__ tok)
{
    int i = blockIdx.x * 256 + threadIdx.x;      // 4*4*384 = 6144
    if (i >= BB * 4 * DD) return;
    int b = i / (4 * DD);
    int r = i % (4 * DD);                        // s*384 + d
    tok[(size_t)(b * TT) * DD + r] = skills[r];
}

// ---------------- layernorm (384 cols, 128 threads/row) ----------------
__global__ void __launch_bounds__(128) ln_kernel(
    const float* __restrict__ X, const float* __restrict__ gw,
    const float* __restrict__ bw, float* __restrict__ Y)
{
    int row = blockIdx.x;
    int tid = threadIdx.x;
    const float* x = X + (size_t)row * DD;
    float v0 = x[tid], v1 = x[tid + 128], v2 = x[tid + 256];
    float s = v0 + v1 + v2;
    float q = v0 * v0 + v1 * v1 + v2 * v2;
#pragma unroll
    for (int o = 16; o; o >>= 1) {
        s += __shfl_xor_sync(0xffffffffu, s, o);
        q += __shfl_xor_sync(0xffffffffu, q, o);
    }
    __shared__ float ss[4], qq[4];
    if ((tid & 31) == 0) { ss[tid >> 5] = s; qq[tid >> 5] = q; }
    __syncthreads();
    s = ss[0] + ss[1] + ss[2] + ss[3];
    q = qq[0] + qq[1] + qq[2] + qq[3];
    float mean = s * (1.f / DD);
    float var = q * (1.f / DD) - mean * mean;
    float inv = rsqrtf(var + 1e-6f);
    float* y = Y + (size_t)row * DD;
    y[tid]       = (v0 - mean) * inv * gw[tid]       + bw[tid];
    y[tid + 128] = (v1 - mean) * inv * gw[tid + 128] + bw[tid + 128];
    y[tid + 256] = (v2 - mean) * inv * gw[tid + 256] + bw[tid + 256];
}

// ---------------- repack qkv -> q(BH,T,96), kT(BH,96,T), v(BH,T,96) ----------------
__global__ void repack_qkv_kernel(const float* __restrict__ qkv,
                                  float* __restrict__ q, float* __restrict__ kT,
                                  float* __restrict__ v)
{
    int i = blockIdx.x * 256 + threadIdx.x;
    if (i >= ROWS * 3 * DD) return;
    int r = i / (3 * DD), c = i % (3 * DD);
    int s = c / DD, hh = (c % DD) / DH, d = c % DH;
    int b = r / TT, t = r % TT;
    int bh = b * HH + hh;
    float val = qkv[i];
    if (s == 0)      q [((size_t)bh * TT + t) * DH + d] = val;
    else if (s == 1) kT[((size_t)bh * DH + d) * TT + t] = val;
    else             v [((size_t)bh * TT + t) * DH + d] = val;
}

// ---------------- softmax over 260 cols ----------------
__global__ void __launch_bounds__(128) softmax260_kernel(float* __restrict__ S)
{
    int row = blockIdx.x;
    float* p = S + (size_t)row * TT;
    int tid = threadIdx.x;
    float v0 = p[tid], v1 = p[tid + 128];
    float v2 = (tid < 4) ? p[tid + 256] : -1e30f;
    float mx = fmaxf(fmaxf(v0, v1), v2);
#pragma unroll
    for (int o = 16; o; o >>= 1) mx = fmaxf(mx, __shfl_xor_sync(0xffffffffu, mx, o));
    __shared__ float sm[4];
    if ((tid & 31) == 0) sm[tid >> 5] = mx;
    __syncthreads();
    mx = fmaxf(fmaxf(sm[0], sm[1]), fmaxf(sm[2], sm[3]));
    float e0 = __expf(v0 - mx), e1 = __expf(v1 - mx);
    float e2 = (tid < 4) ? __expf(v2 - mx) : 0.f;
    float s = e0 + e1 + e2;
#pragma unroll
    for (int o = 16; o; o >>= 1) s += __shfl_xor_sync(0xffffffffu, s, o);
    __shared__ float sq[4];
    if ((tid & 31) == 0) sq[tid >> 5] = s;
    __syncthreads();
    s = sq[0] + sq[1] + sq[2] + sq[3];
    float inv = __fdividef(1.f, s);
    p[tid] = e0 * inv;
    p[tid + 128] = e1 * inv;
    if (tid < 4) p[tid + 256] = e2 * inv;
}

// ---------------- compute w = softmax(mean(tok[:, :4]) @ mk^T / sqrt(D)) ----------------
__global__ void compute_w_kernel(const float* __restrict__ tok,
                                 const float* __restrict__ mk,
                                 float* __restrict__ wout)
{
    int tid = threadIdx.x;            // 32 threads: (b = tid>>3, m = tid&7)
    int b = tid >> 3, m = tid & 7;
    float acc = 0.f;
    const float* t0 = tok + (size_t)(b * TT + 0) * DD;
    const float* t1 = tok + (size_t)(b * TT + 1) * DD;
    const float* t2 = tok + (size_t)(b * TT + 2) * DD;
    const float* t3 = tok + (size_t)(b * TT + 3) * DD;
    const float* key = mk + (size_t)m * DD;
    for (int d = 0; d < DD; d++) {
        float qt = 0.25f * (t0[d] + t1[d] + t2[d] + t3[d]);
        acc = fmaf(qt, key[d], acc);
    }
    float logit = acc * 0.05103103630798288f;   // 1/sqrt(384)
    float mx = logit;
#pragma unroll
    for (int o = 4; o; o >>= 1) mx = fmaxf(mx, __shfl_xor_sync(0xffffffffu, mx, o));
    float e = __expf(logit - mx);
    float s = e;
#pragma unroll
    for (int o = 4; o; o >>= 1) s += __shfl_xor_sync(0xffffffffu, s, o);
    wout[tid] = e / s;
}

// ---------------- hard-concrete + delta contraction (the big one) ----------------
__device__ __forceinline__ float hc_z(float u, float la)
{
    u = fminf(fmaxf(u, 1e-6f), 1.0f - 1e-6f);
    // t = (ln u - ln(1-u) + la) / beta, beta = 2/3
    float t = (__logf(u) - __logf(1.0f - u) + la) * 1.5f;
    float x = __expf(-t);                        // s = 1/(1+x)
    // z = clip(1.2*s - 0.1) = clip((1.1 - 0.1x)/(1+x))
    float num = fmaf(-0.1f, x, 1.1f);
    float z = __fdividef(num, 1.0f + x);
    return fminf(fmaxf(z, 0.0f), 1.0f);
}

__global__ void __launch_bounds__(256) delta_kernel(
    const float* __restrict__ u_a, const float* __restrict__ la_a, const float* __restrict__ phi_a,
    const float* __restrict__ u_b, const float* __restrict__ la_b, const float* __restrict__ phi_b,
    const float* __restrict__ wbuf, float* __restrict__ out)
{
    __shared__ float ws[32];
    if (threadIdx.x < 32) ws[threadIdx.x] = wbuf[threadIdx.x];
    __syncthreads();

    int g = blockIdx.x * 256 + threadIdx.x;      // [0, 2*GCNT)
    bool isB = g >= GCNT;
    int gg = isB ? g - GCNT : g;
    const float* up = isB ? u_b : u_a;
    const float* lp = isB ? la_b : la_a;
    const float* pp = isB ? phi_b : phi_a;

    size_t e8 = (size_t)gg * 8;
    float4 u0 = *(const float4*)(up + e8);
    float4 u1 = *(const float4*)(up + e8 + 4);
    float4 l0 = *(const float4*)(lp + e8);
    float4 l1 = *(const float4*)(lp + e8 + 4);
    float phi = pp[gg];

    float z[8];
    z[0] = hc_z(u0.x, l0.x); z[1] = hc_z(u0.y, l0.y);
    z[2] = hc_z(u0.z, l0.z); z[3] = hc_z(u0.w, l0.w);
    z[4] = hc_z(u1.x, l1.x); z[5] = hc_z(u1.y, l1.y);
    z[6] = hc_z(u1.z, l1.z); z[7] = hc_z(u1.w, l1.w);

    size_t base = (size_t)(isB ? GCNT : 0) + (size_t)gg;
#pragma unroll
    for (int b = 0; b < 4; b++) {
        float acc = 0.f;
#pragma unroll
        for (int m = 0; m < 8; m++) acc = fmaf(z[m], ws[b * 8 + m], acc);
        out[(size_t)b * OUTROW + base] = acc * phi;
    }
}

// ---------------- host launch ----------------
extern "C" void kernel_launch(void* const* d_in, const int* in_sizes, int n_in,
                              void* d_out, int out_size)
{
    const float* x      = (const float*)d_in[0];
    const float* u_a    = (const float*)d_in[1];
    const float* u_b    = (const float*)d_in[2];
    const float* phi_a  = (const float*)d_in[3];
    const float* phi_b  = (const float*)d_in[4];
    const float* la_a   = (const float*)d_in[5];
    const float* la_b   = (const float*)d_in[6];
    const float* Wp     = (const float*)d_in[7];
    const float* bp     = (const float*)d_in[8];
    const float* skills = (const float*)d_in[9];
    const float* cenc   = (const float*)d_in[10];
    const float* ln1_g  = (const float*)d_in[11];
    const float* ln1_b  = (const float*)d_in[12];
    const float* Wqkv   = (const float*)d_in[13];
    const float* bqkv   = (const float*)d_in[14];
    const float* Wo     = (const float*)d_in[15];
    const float* bo     = (const float*)d_in[16];
    const float* ln2_g  = (const float*)d_in[17];
    const float* ln2_b  = (const float*)d_in[18];
    const float* W1     = (const float*)d_in[19];
    const float* b1     = (const float*)d_in[20];
    const float* W2     = (const float*)d_in[21];
    const float* b2     = (const float*)d_in[22];
    const float* mk     = (const float*)d_in[23];
    float* out = (float*)d_out;

    float* scratch = nullptr;
    cudaGetSymbolAddress((void**)&scratch, g_scratch);
    float* tok  = scratch + OFF_TOK;
    float* ybuf = scratch + OFF_Y;
    float* qkv  = scratch + OFF_QKV;
    float* qb   = scratch + OFF_Q;
    float* kT   = scratch + OFF_KT;
    float* vb   = scratch + OFF_V;
    float* sc   = scratch + OFF_SC;
    float* ob   = scratch + OFF_O;
    float* ff   = scratch + OFF_FF;
    float* wbuf = scratch + OFF_W;

    // 1. h = x@Wp + bp + count_enc  -> tok rows [4:260) per batch (batched over B)
    gemm_kernel<<<dim3(DD / 64, NN / 64, BB), 256>>>(
        x, Wp, bp, cenc, tok + 4 * DD,
        NN, DD, DD,
        (long long)NN * DD, 0LL, (long long)TT * DD, 0LL, 1,
        DD, 1.0f, 2);

    // 2. skill tokens
    fill_skills_kernel<<<(BB * 4 * DD + 255) / 256, 256>>>(skills, tok);

    // 3. LN1
    ln_kernel<<<ROWS, 128>>>(tok, ln1_g, ln1_b, ybuf);

    // 4. qkv = y @ Wqkv + bqkv
    gemm_kernel<<<dim3(3 * DD / 64, (ROWS + 63) / 64, 1), 256>>>(
        ybuf, Wqkv, bqkv, nullptr, qkv,
        ROWS, 3 * DD, DD,
        0LL, 0LL, 0LL, 0LL, 1,
        3 * DD, 1.0f, 0);

    // 5. repack to q/kT/v per (b,h)
    repack_qkv_kernel<<<(ROWS * 3 * DD + 255) / 256, 256>>>(qkv, qb, kT, vb);

    // 6. scores = q @ kT / sqrt(96)   (batched over BH=16)
    gemm_kernel<<<dim3((TT + 63) / 64, (TT + 63) / 64, BB * HH), 256>>>(
        qb, kT, nullptr, nullptr, sc,
        TT, TT, DH,
        (long long)TT * DH, (long long)TT * DH, (long long)TT * TT, 0LL, 1,
        TT, 0.10206207261596577f, 0);

    // 7. softmax over k
    softmax260_kernel<<<BB * HH * TT, 128>>>(sc);

    // 8. o = att @ v, written directly in (B,T,D) layout
    gemm_kernel<<<dim3((DH + 63) / 64, (TT + 63) / 64, BB * HH), 256>>>(
        sc, vb, nullptr, nullptr, ob,
        TT, DH, TT,
        (long long)TT * TT, (long long)TT * DH,
        (long long)TT * DD, (long long)DH, HH,
        DD, 1.0f, 0);

    // 9. tok += o @ Wo + bo
    gemm_kernel<<<dim3(DD / 64, (ROWS + 63) / 64, 1), 256>>>(
        ob, Wo, bo, tok, tok,
        ROWS, DD, DD,
        0LL, 0LL, 0LL, 0LL, 1,
        DD, 1.0f, 3);

    // 10. LN2
    ln_kernel<<<ROWS, 128>>>(tok, ln2_g, ln2_b, ybuf);

    // 11. ff = gelu(y @ W1 + b1)
    gemm_kernel<<<dim3(2 * DD / 64, (ROWS + 63) / 64, 1), 256>>>(
        ybuf, W1, b1, nullptr, ff,
        ROWS, 2 * DD, DD,
        0LL, 0LL, 0LL, 0LL, 1,
        2 * DD, 1.0f, 1);

    // 12. tok += ff @ W2 + b2
    gemm_kernel<<<dim3(DD / 64, (ROWS + 63) / 64, 1), 256>>>(
        ff, W2, b2, tok, tok,
        ROWS, DD, 2 * DD,
        0LL, 0LL, 0LL, 0LL, 1,
        DD, 1.0f, 3);

    // 13. w = softmax(mean(tok[:, :4]) @ mk^T / sqrt(D))
    compute_w_kernel<<<1, 32>>>(tok, mk, wbuf);

    // 14. hard-concrete + contraction (the HBM-bound bulk)
    delta_kernel<<<(2 * GCNT) / 256, 256>>>(
        u_a, la_a, phi_a, u_b, la_b, phi_b, wbuf, out);
}

// round 2
// speedup vs baseline: 1.0923x; 1.0923x over previous
#include <cuda_runtime.h>
#include <cuda_bf16.h>
#include <math.h>

// ---------------- problem constants ----------------
#define BB   4
#define NN   256
#define DD   384
#define LL   12
#define F1C  1536
#define F2C  384
#define MM   8
#define HH   4
#define TT   260          // 4 skill tokens + 256
#define DH   96           // D / H
#define ROWS (BB*TT)      // 1040

#define GCNT   (LL*F1C*F2C)          // 7,077,888
#define OUTROW (2LL*GCNT)            // 14,155,776 per batch row

// ---------------- device scratch (static, no allocation) ----------------
#define OFF_TOK  0
#define SZ_TOK   (ROWS*DD)
#define OFF_Y    (OFF_TOK + SZ_TOK)
#define SZ_Y     (ROWS*DD)
#define OFF_Q    (OFF_Y + SZ_Y)
#define SZ_Q     (BB*HH*TT*DH)             // 399360
#define OFF_KT   (OFF_Q + SZ_Q)
#define SZ_KT    (BB*HH*TT*DH)
#define OFF_V    (OFF_KT + SZ_KT)
#define SZ_V     (BB*HH*TT*DH)
#define OFF_SC   (OFF_V + SZ_V)
#define SZ_SC    (BB*HH*TT*TT)             // 1081600
#define OFF_O    (OFF_SC + SZ_SC)
#define SZ_O     (ROWS*DD)
#define OFF_FF   (OFF_O + SZ_O)
#define SZ_FF    (ROWS*2*DD)
#define OFF_W    (OFF_FF + SZ_FF)
#define SZ_W     32
#define SCRATCH_TOTAL (OFF_W + SZ_W)

__device__ float g_scratch[SCRATCH_TOTAL];

// ---------------- generic batched GEMM with register double-buffering ----------------
// C = act(scale*(A@W) + bias [+R])
// A: (Mr x K) row-major, lda=K.  W: (K x N) row-major.  C: ldc row stride.
// batch z: A += z*aBS, W += z*wBS, C += (z/cdiv)*cBS1 + (z%cdiv)*cBS2
// epi: 0=none, 1=gelu(tanh), 2=+R[col] broadcast, 3=+R[coff + row*ldc + col] residual,
//      4=qkv scatter (C=qbase; kT=C+SZ_Q; v=C+2*SZ_Q)
__global__ void __launch_bounds__(256) gemm_kernel(
    const float* __restrict__ A, const float* __restrict__ W,
    const float* __restrict__ bias, const float* __restrict__ R,
    float* __restrict__ C,
    int Mr, int N, int K,
    long long aBS, long long wBS, long long cBS1, long long cBS2, int cdiv,
    int ldc, float scale, int epi)
{
    int z = blockIdx.z;
    A += (size_t)z * aBS;
    W += (size_t)z * wBS;
    size_t coff = (size_t)(z / cdiv) * cBS1 + (size_t)(z % cdiv) * cBS2;
    C += coff;
    const float* Rm = (epi == 3) ? (R + coff) : R;

    __shared__ float As[16][64];   // transposed: [k][m]
    __shared__ float Ws[16][64];   // [k][n]

    int bm = blockIdx.y * 64, bn = blockIdx.x * 64;
    int tid = threadIdx.x;
    int tx = tid & 15, ty = tid >> 4;

    // A-load mapping: conflict-free STS (warp covers 32 consecutive rows)
    int la_m = tid & 63;            // row in tile
    int la_k = (tid >> 6) << 2;     // 0,4,8,12
    int lw_k = tid >> 4;            // 0..15
    int lw_n = (tid & 15) << 2;     // 0..60

    int arow = bm + la_m;
    bool a_ok = arow < Mr;
    const float* Aptr = A + (size_t)(a_ok ? arow : 0) * K;
    bool w_col_ok = (bn + lw_n) < N;
    const float* Wptr = W + bn + lw_n;

    float acc[4][4];
#pragma unroll
    for (int i = 0; i < 4; i++)
#pragma unroll
        for (int j = 0; j < 4; j++) acc[i][j] = 0.f;

    // prologue: load first K-slice into registers
    float4 av = make_float4(0.f, 0.f, 0.f, 0.f);
    float4 wv = make_float4(0.f, 0.f, 0.f, 0.f);
    if (a_ok && la_k < K) av = *(const float4*)(Aptr + la_k);
    if (w_col_ok && lw_k < K) wv = *(const float4*)(Wptr + (size_t)lw_k * N);

    for (int k0 = 0; k0 < K; k0 += 16) {
        // stage registers -> smem
        As[la_k + 0][la_m] = av.x;
        As[la_k + 1][la_m] = av.y;
        As[la_k + 2][la_m] = av.z;
        As[la_k + 3][la_m] = av.w;
        *(float4*)&Ws[lw_k][lw_n] = wv;
        __syncthreads();

        // prefetch next K-slice (latency hidden behind compute below)
        int kn = k0 + 16;
        if (kn < K) {
            av = make_float4(0.f, 0.f, 0.f, 0.f);
            wv = make_float4(0.f, 0.f, 0.f, 0.f);
            if (a_ok && (kn + la_k) < K) av = *(const float4*)(Aptr + kn + la_k);
            if (w_col_ok && (kn + lw_k) < K) wv = *(const float4*)(Wptr + (size_t)(kn + lw_k) * N);
        }

#pragma unroll
        for (int kk = 0; kk < 16; kk++) {
            float4 a = *(const float4*)&As[kk][ty << 2];
            float4 w = *(const float4*)&Ws[kk][tx << 2];
            acc[0][0] = fmaf(a.x, w.x, acc[0][0]);
            acc[0][1] = fmaf(a.x, w.y, acc[0][1]);
            acc[0][2] = fmaf(a.x, w.z, acc[0][2]);
            acc[0][3] = fmaf(a.x, w.w, acc[0][3]);
            acc[1][0] = fmaf(a.y, w.x, acc[1][0]);
            acc[1][1] = fmaf(a.y, w.y, acc[1][1]);
            acc[1][2] = fmaf(a.y, w.z, acc[1][2]);
            acc[1][3] = fmaf(a.y, w.w, acc[1][3]);
            acc[2][0] = fmaf(a.z, w.x, acc[2][0]);
            acc[2][1] = fmaf(a.z, w.y, acc[2][1]);
            acc[2][2] = fmaf(a.z, w.z, acc[2][2]);
            acc[2][3] = fmaf(a.z, w.w, acc[2][3]);
            acc[3][0] = fmaf(a.w, w.x, acc[3][0]);
            acc[3][1] = fmaf(a.w, w.y, acc[3][1]);
            acc[3][2] = fmaf(a.w, w.z, acc[3][2]);
            acc[3][3] = fmaf(a.w, w.w, acc[3][3]);
        }
        __syncthreads();
    }

    int colb = bn + (tx << 2);
    if (colb >= N) return;
    float4 bv = make_float4(0.f, 0.f, 0.f, 0.f);
    if (bias) bv = *(const float4*)(bias + colb);
    float4 ev = make_float4(0.f, 0.f, 0.f, 0.f);
    if (epi == 2) ev = *(const float4*)(R + colb);

    float* qb_  = C;
    float* kTb_ = C + SZ_Q;
    float* vb_  = C + 2 * SZ_Q;

#pragma unroll
    for (int i = 0; i < 4; i++) {
        int row = bm + (ty << 2) + i;
        if (row >= Mr) continue;
        float4 r;
        r.x = acc[i][0] * scale + bv.x;
        r.y = acc[i][1] * scale + bv.y;
        r.z = acc[i][2] * scale + bv.z;
        r.w = acc[i][3] * scale + bv.w;
        if (epi == 1) {
            float v;
            v = r.x; r.x = 0.5f * v * (1.f + tanhf(0.7978845608028654f * (v + 0.044715f * v * v * v)));
            v = r.y; r.y = 0.5f * v * (1.f + tanhf(0.7978845608028654f * (v + 0.044715f * v * v * v)));
            v = r.z; r.z = 0.5f * v * (1.f + tanhf(0.7978845608028654f * (v + 0.044715f * v * v * v)));
            v = r.w; r.w = 0.5f * v * (1.f + tanhf(0.7978845608028654f * (v + 0.044715f * v * v * v)));
        } else if (epi == 2) {
            r.x += ev.x; r.y += ev.y; r.z += ev.z; r.w += ev.w;
        } else if (epi == 3) {
            float4 rv = *(const float4*)(Rm + (size_t)row * ldc + colb);
            r.x += rv.x; r.y += rv.y; r.z += rv.z; r.w += rv.w;
        }
        if (epi == 4) {
            // scatter qkv: col -> (s, h, d); row -> (b, t)
            int b = row / TT, t = row - b * TT;
            float rv[4] = {r.x, r.y, r.z, r.w};
#pragma unroll
            for (int j = 0; j < 4; j++) {
                int c = colb + j;
                int s = c / DD;
                int rem = c - s * DD;
                int h = rem / DH;
                int d = rem - h * DH;
                int bh = b * HH + h;
                if (s == 0)      qb_ [((size_t)bh * TT + t) * DH + d] = rv[j];
                else if (s == 1) kTb_[((size_t)bh * DH + d) * TT + t] = rv[j];
                else             vb_ [((size_t)bh * TT + t) * DH + d] = rv[j];
            }
        } else {
            *(float4*)(C + (size_t)row * ldc + colb) = r;
        }
    }
}

// ---------------- fill skill tokens ----------------
__global__ void fill_skills_kernel(const float* __restrict__ skills, float* __restrict__ tok)
{
    int i = blockIdx.x * 256 + threadIdx.x;
    if (i >= BB * 4 * DD) return;
    int b = i / (4 * DD);
    int r = i % (4 * DD);
    tok[(size_t)(b * TT) * DD + r] = skills[r];
}

// ---------------- layernorm (384 cols, 128 threads/row) ----------------
__global__ void __launch_bounds__(128) ln_kernel(
    const float* __restrict__ X, const float* __restrict__ gw,
    const float* __restrict__ bw, float* __restrict__ Y)
{
    int row = blockIdx.x;
    int tid = threadIdx.x;
    const float* x = X + (size_t)row * DD;
    float v0 = x[tid], v1 = x[tid + 128], v2 = x[tid + 256];
    float s = v0 + v1 + v2;
    float q = v0 * v0 + v1 * v1 + v2 * v2;
#pragma unroll
    for (int o = 16; o; o >>= 1) {
        s += __shfl_xor_sync(0xffffffffu, s, o);
        q += __shfl_xor_sync(0xffffffffu, q, o);
    }
    __shared__ float ss[4], qq[4];
    if ((tid & 31) == 0) { ss[tid >> 5] = s; qq[tid >> 5] = q; }
    __syncthreads();
    s = ss[0] + ss[1] + ss[2] + ss[3];
    q = qq[0] + qq[1] + qq[2] + qq[3];
    float mean = s * (1.f / DD);
    float var = q * (1.f / DD) - mean * mean;
    float inv = rsqrtf(var + 1e-6f);
    float* y = Y + (size_t)row * DD;
    y[tid]       = (v0 - mean) * inv * gw[tid]       + bw[tid];
    y[tid + 128] = (v1 - mean) * inv * gw[tid + 128] + bw[tid + 128];
    y[tid + 256] = (v2 - mean) * inv * gw[tid + 256] + bw[tid + 256];
}

// ---------------- softmax over 260 cols ----------------
__global__ void __launch_bounds__(128) softmax260_kernel(float* __restrict__ S)
{
    int row = blockIdx.x;
    float* p = S + (size_t)row * TT;
    int tid = threadIdx.x;
    float v0 = p[tid], v1 = p[tid + 128];
    float v2 = (tid < 4) ? p[tid + 256] : -1e30f;
    float mx = fmaxf(fmaxf(v0, v1), v2);
#pragma unroll
    for (int o = 16; o; o >>= 1) mx = fmaxf(mx, __shfl_xor_sync(0xffffffffu, mx, o));
    __shared__ float sm[4];
    if ((tid & 31) == 0) sm[tid >> 5] = mx;
    __syncthreads();
    mx = fmaxf(fmaxf(sm[0], sm[1]), fmaxf(sm[2], sm[3]));
    float e0 = __expf(v0 - mx), e1 = __expf(v1 - mx);
    float e2 = (tid < 4) ? __expf(v2 - mx) : 0.f;
    float s = e0 + e1 + e2;
#pragma unroll
    for (int o = 16; o; o >>= 1) s += __shfl_xor_sync(0xffffffffu, s, o);
    __shared__ float sq[4];
    if ((tid & 31) == 0) sq[tid >> 5] = s;
    __syncthreads();
    s = sq[0] + sq[1] + sq[2] + sq[3];
    float inv = __fdividef(1.f, s);
    p[tid] = e0 * inv;
    p[tid + 128] = e1 * inv;
    if (tid < 4) p[tid + 256] = e2 * inv;
}

// ---------------- w = softmax(mean(tok[:, :4]) @ mk^T / sqrt(D)), 256 threads ----------------
__global__ void __launch_bounds__(256) compute_w_kernel(
    const float* __restrict__ tok, const float* __restrict__ mk,
    float* __restrict__ wout)
{
    int tid = threadIdx.x;
    int p = tid >> 3;              // pair 0..31: b = p>>3, m = p&7
    int b = p >> 3, m = p & 7;
    int j = tid & 7;
    const float* tb = tok + (size_t)b * TT * DD;
    const float* key = mk + (size_t)m * DD;
    float acc = 0.f;
    for (int d = j * 4; d < DD; d += 32) {
        float4 k4 = *(const float4*)(key + d);
        float4 t0 = *(const float4*)(tb + d);
        float4 t1 = *(const float4*)(tb + DD + d);
        float4 t2 = *(const float4*)(tb + 2 * DD + d);
        float4 t3 = *(const float4*)(tb + 3 * DD + d);
        acc = fmaf(0.25f * (t0.x + t1.x + t2.x + t3.x), k4.x, acc);
        acc = fmaf(0.25f * (t0.y + t1.y + t2.y + t3.y), k4.y, acc);
        acc = fmaf(0.25f * (t0.z + t1.z + t2.z + t3.z), k4.z, acc);
        acc = fmaf(0.25f * (t0.w + t1.w + t2.w + t3.w), k4.w, acc);
    }
    acc += __shfl_xor_sync(0xffffffffu, acc, 4);
    acc += __shfl_xor_sync(0xffffffffu, acc, 2);
    acc += __shfl_xor_sync(0xffffffffu, acc, 1);
    __shared__ float sl[32];
    if (j == 0) sl[p] = acc * 0.05103103630798288f;   // 1/sqrt(384)
    __syncthreads();
    if (tid < 32) {
        float logit = sl[tid];
        float mx = logit;
#pragma unroll
        for (int o = 4; o; o >>= 1) mx = fmaxf(mx, __shfl_xor_sync(0xffffffffu, mx, o));
        float e = __expf(logit - mx);
        float s = e;
#pragma unroll
        for (int o = 4; o; o >>= 1) s += __shfl_xor_sync(0xffffffffu, s, o);
        wout[tid] = e / s;
    }
}

// ---------------- hard-concrete + delta contraction (HBM-bound bulk) ----------------
__device__ __forceinline__ float hc_z(float u, float la)
{
    u = fminf(fmaxf(u, 1e-6f), 1.0f - 1e-6f);
    float t = (__logf(u) - __logf(1.0f - u) + la) * 1.5f;
    float x = __expf(-t);
    float num = fmaf(-0.1f, x, 1.1f);
    float z = __fdividef(num, 1.0f + x);
    return fminf(fmaxf(z, 0.0f), 1.0f);
}

__global__ void __launch_bounds__(256) delta_kernel(
    const float* __restrict__ u_a, const float* __restrict__ la_a, const float* __restrict__ phi_a,
    const float* __restrict__ u_b, const float* __restrict__ la_b, const float* __restrict__ phi_b,
    const float* __restrict__ wbuf, float* __restrict__ out)
{
    __shared__ float ws[32];
    if (threadIdx.x < 32) ws[threadIdx.x] = wbuf[threadIdx.x];
    __syncthreads();

    int g = blockIdx.x * 256 + threadIdx.x;
    bool isB = g >= GCNT;
    int gg = isB ? g - GCNT : g;
    const float* up = isB ? u_b : u_a;
    const float* lp = isB ? la_b : la_a;
    const float* pp = isB ? phi_b : phi_a;

    size_t e8 = (size_t)gg * 8;
    float4 u0 = __ldcs((const float4*)(up + e8));
    float4 u1 = __ldcs((const float4*)(up + e8 + 4));
    float4 l0 = __ldcs((const float4*)(lp + e8));
    float4 l1 = __ldcs((const float4*)(lp + e8 + 4));
    float phi = __ldcs(pp + gg);

    float z[8];
    z[0] = hc_z(u0.x, l0.x); z[1] = hc_z(u0.y, l0.y);
    z[2] = hc_z(u0.z, l0.z); z[3] = hc_z(u0.w, l0.w);
    z[4] = hc_z(u1.x, l1.x); z[5] = hc_z(u1.y, l1.y);
    z[6] = hc_z(u1.z, l1.z); z[7] = hc_z(u1.w, l1.w);

    size_t base = (size_t)(isB ? GCNT : 0) + (size_t)gg;
#pragma unroll
    for (int b = 0; b < 4; b++) {
        float acc = 0.f;
#pragma unroll
        for (int m = 0; m < 8; m++) acc = fmaf(z[m], ws[b * 8 + m], acc);
        __stcs(out + (size_t)b * OUTROW + base, acc * phi);
    }
}

// ---------------- host launch ----------------
extern "C" void kernel_launch(void* const* d_in, const int* in_sizes, int n_in,
                              void* d_out, int out_size)
{
    const float* x      = (const float*)d_in[0];
    const float* u_a    = (const float*)d_in[1];
    const float* u_b    = (const float*)d_in[2];
    const float* phi_a  = (const float*)d_in[3];
    const float* phi_b  = (const float*)d_in[4];
    const float* la_a   = (const float*)d_in[5];
    const float* la_b   = (const float*)d_in[6];
    const float* Wp     = (const float*)d_in[7];
    const float* bp     = (const float*)d_in[8];
    const float* skills = (const float*)d_in[9];
    const float* cenc   = (const float*)d_in[10];
    const float* ln1_g  = (const float*)d_in[11];
    const float* ln1_b  = (const float*)d_in[12];
    const float* Wqkv   = (const float*)d_in[13];
    const float* bqkv   = (const float*)d_in[14];
    const float* Wo     = (const float*)d_in[15];
    const float* bo     = (const float*)d_in[16];
    const float* ln2_g  = (const float*)d_in[17];
    const float* ln2_b  = (const float*)d_in[18];
    const float* W1     = (const float*)d_in[19];
    const float* b1     = (const float*)d_in[20];
    const float* W2     = (const float*)d_in[21];
    const float* b2     = (const float*)d_in[22];
    const float* mk     = (const float*)d_in[23];
    float* out = (float*)d_out;

    float* scratch = nullptr;
    cudaGetSymbolAddress((void**)&scratch, g_scratch);
    float* tok  = scratch + OFF_TOK;
    float* ybuf = scratch + OFF_Y;
    float* qb   = scratch + OFF_Q;
    float* sc   = scratch + OFF_SC;
    float* ob   = scratch + OFF_O;
    float* ff   = scratch + OFF_FF;
    float* wbuf = scratch + OFF_W;
    float* kT   = scratch + OFF_KT;
    float* vb   = scratch + OFF_V;

    // 1. h = x@Wp + bp + count_enc  -> tok rows [4:260)
    gemm_kernel<<<dim3(DD / 64, NN / 64, BB), 256>>>(
        x, Wp, bp, cenc, tok + 4 * DD,
        NN, DD, DD,
        (long long)NN * DD, 0LL, (long long)TT * DD, 0LL, 1,
        DD, 1.0f, 2);

    // 2. skill tokens
    fill_skills_kernel<<<(BB * 4 * DD + 255) / 256, 256>>>(skills, tok);

    // 3. LN1
    ln_kernel<<<ROWS, 128>>>(tok, ln1_g, ln1_b, ybuf);

    // 4. qkv = y @ Wqkv + bqkv, scattered directly to q / kT / v (epi=4)
    gemm_kernel<<<dim3(3 * DD / 64, (ROWS + 63) / 64, 1), 256>>>(
        ybuf, Wqkv, bqkv, nullptr, qb,
        ROWS, 3 * DD, DD,
        0LL, 0LL, 0LL, 0LL, 1,
        0, 1.0f, 4);

    // 5. scores = q @ kT / sqrt(96)   (batched over BH=16)
    gemm_kernel<<<dim3((TT + 63) / 64, (TT + 63) / 64, BB * HH), 256>>>(
        qb, kT, nullptr, nullptr, sc,
        TT, TT, DH,
        (long long)TT * DH, (long long)TT * DH, (long long)TT * TT, 0LL, 1,
        TT, 0.10206207261596577f, 0);

    // 6. softmax over k
    softmax260_kernel<<<BB * HH * TT, 128>>>(sc);

    // 7. o = att @ v, written directly in (B,T,D) layout
    gemm_kernel<<<dim3((DH + 63) / 64, (TT + 63) / 64, BB * HH), 256>>>(
        sc, vb, nullptr, nullptr, ob,
        TT, DH, TT,
        (long long)TT * TT, (long long)TT * DH,
        (long long)TT * DD, (long long)DH, HH,
        DD, 1.0f, 0);

    // 8. tok += o @ Wo + bo
    gemm_kernel<<<dim3(DD / 64, (ROWS + 63) / 64, 1), 256>>>(
        ob, Wo, bo, tok, tok,
        ROWS, DD, DD,
        0LL, 0LL, 0LL, 0LL, 1,
        DD, 1.0f, 3);

    // 9. LN2
    ln_kernel<<<ROWS, 128>>>(tok, ln2_g, ln2_b, ybuf);

    // 10. ff = gelu(y @ W1 + b1)
    gemm_kernel<<<dim3(2 * DD / 64, (ROWS + 63) / 64, 1), 256>>>(
        ybuf, W1, b1, nullptr, ff,
        ROWS, 2 * DD, DD,
        0LL, 0LL, 0LL, 0LL, 1,
        2 * DD, 1.0f, 1);

    // 11. tok += ff @ W2 + b2
    gemm_kernel<<<dim3(DD / 64, (ROWS + 63) / 64, 1), 256>>>(
        ff, W2, b2, tok, tok,
        ROWS, DD, 2 * DD,
        0LL, 0LL, 0LL, 0LL, 1,
        DD, 1.0f, 3);

    // 12. w = softmax(mean(tok[:, :4]) @ mk^T / sqrt(D))
    compute_w_kernel<<<1, 256>>>(tok, mk, wbuf);

    // 13. hard-concrete + contraction
    delta_kernel<<<(2 * GCNT) / 256, 256>>>(
        u_a, la_a, phi_a, u_b, la_b, phi_b, wbuf, out);
}